// round 6
// baseline (speedup 1.0000x reference)
#include <cuda_runtime.h>

typedef unsigned long long ull;

__device__ __forceinline__ ull pk(float lo, float hi) {
    ull r; asm("mov.b64 %0,{%1,%2};" : "=l"(r) : "f"(lo), "f"(hi)); return r;
}
__device__ __forceinline__ void upk(ull v, float& lo, float& hi) {
    asm("mov.b64 {%0,%1},%2;" : "=f"(lo), "=f"(hi) : "l"(v));
}
__device__ __forceinline__ void ffma2(ull& d, ull a, ull b) {
    asm("fma.rn.f32x2 %0,%1,%2,%0;" : "+l"(d) : "l"(a), "l"(b));
}

// ---------------- constants ----------------
constexpr int F = 114176;
constexpr int OW0 = 0, OB0 = 1728, OW1 = 1792, OB1 = 38656, OW2 = 38720,
              OB2 = 75584, OW3 = 75648, OB3 = 112512, OFC = 112576;
constexpr int WTS = 64*64*9;

// ---------------- scratch ----------------
__device__ float g_x  [128*3*84*84];
__device__ float g_p0 [128*64*42*42];
__device__ float g_dp0[128*64*42*42];
__device__ unsigned char g_i0[128*64*42*42];
__device__ float g_p1 [128*64*21*21];
__device__ float g_dp1[128*64*21*21];
__device__ unsigned char g_i1[128*64*21*21];
__device__ float g_p2 [128*64*10*10];
__device__ float g_d3 [128*64*10*10];
__device__ float g_dp2[128*64*10*10];
__device__ unsigned char g_i2[128*64*10*10];
__device__ float g_p3 [128*64*5*5];
__device__ unsigned char g_i3[128*64*5*5];
__device__ float g_wt [3*WTS];
__device__ float g_G  [128*(size_t)F];
__device__ float g_part[8*4096];

// ---------------- kernels ----------------
__global__ void pack_x_k(const float* __restrict__ x1, const float* __restrict__ x2,
                         float* __restrict__ xo) {
    int t = blockIdx.x*256 + threadIdx.x;
    const int P = 3*84*84;
    if (t >= 128*P) return;
    int n = t / P, k = t - n*P;
    xo[t] = (n < 64) ? x1[n*P + k] : x2[(n-64)*P + k];
}

// smem-staged fused conv3x3(SAME)+bias+relu+2x2 maxpool.
// block = (strip of TR tile rows, oc group of 8, n); double-buffered input strip.
template<int IC>
__launch_bounds__(128)
__global__ void convpool_sm_k(const float* __restrict__ in, const float* __restrict__ w,
                              const float* __restrict__ bias, float* __restrict__ p,
                              unsigned char* __restrict__ idx,
                              int H, int W, int Hp, int Wp, int TR)
{
    const int n = blockIdx.z, oc0 = blockIdx.y*8, tr0 = blockIdx.x*TR;
    const int W2 = W + 2;
    const int BUFN = (2*TR+2)*W2;
    __shared__ float ws[8*IC*12];
    __shared__ float bs[8];
    extern __shared__ float buf[];   // 2*BUFN floats
    const int tid = threadIdx.x;
    for (int i = tid; i < 8*IC*9; i += 128) {
        int oi = i/9, k = i - oi*9;
        ws[oi*12+k] = w[(size_t)oc0*IC*9 + i];
    }
    if (tid < 8) bs[tid] = bias[oc0+tid];
    const int y_lo = 2*tr0 - 1;
    const float* ip = in + (size_t)n*IC*H*W;
    auto fill = [&](float* b, int ic) {
        const float* pp = ip + (size_t)ic*H*W;
        for (int i = tid; i < BUFN; i += 128) {
            int r = i / W2, c = i - r*W2;
            int y = y_lo + r, x = c - 1;
            b[i] = ((unsigned)y < (unsigned)H && (unsigned)x < (unsigned)W) ? pp[y*W+x] : 0.f;
        }
    };
    fill(buf, 0);
    const int lt = tid, tyl = lt / Wp, tx = lt - tyl*Wp;
    const bool act = (lt < TR*Wp) && (tr0 + tyl < Hp);
    __syncthreads();
    float acc[8][4];
    #pragma unroll
    for (int o = 0; o < 8; o++) {
        float b = bs[o];
        acc[o][0]=b; acc[o][1]=b; acc[o][2]=b; acc[o][3]=b;
    }
    #pragma unroll 1
    for (int ic = 0; ic < IC; ic++) {
        const float* cb = buf + (ic & 1)*BUFN;
        if (ic + 1 < IC) fill(buf + ((ic+1) & 1)*BUFN, ic+1);
        if (act) {
            float v[4][4];
            #pragma unroll
            for (int u = 0; u < 4; u++)
            #pragma unroll
            for (int j = 0; j < 4; j++)
                v[u][j] = cb[(2*tyl+u)*W2 + 2*tx + j];
            #pragma unroll
            for (int o = 0; o < 8; o++) {
                float wr[12];
                *(float4*)&wr[0] = *(const float4*)&ws[(o*IC+ic)*12];
                *(float4*)&wr[4] = *(const float4*)&ws[(o*IC+ic)*12+4];
                wr[8] = ws[(o*IC+ic)*12+8];
                #pragma unroll
                for (int u = 0; u < 3; u++)
                #pragma unroll
                for (int vv = 0; vv < 3; vv++) {
                    float wv = wr[u*3+vv];
                    acc[o][0] += wv*v[u  ][vv  ];
                    acc[o][1] += wv*v[u  ][vv+1];
                    acc[o][2] += wv*v[u+1][vv  ];
                    acc[o][3] += wv*v[u+1][vv+1];
                }
            }
        }
        __syncthreads();
    }
    if (act) {
        const int py = tr0 + tyl;
        #pragma unroll
        for (int o = 0; o < 8; o++) {
            float a0 = fmaxf(acc[o][0],0.f), a1 = fmaxf(acc[o][1],0.f),
                  a2 = fmaxf(acc[o][2],0.f), a3 = fmaxf(acc[o][3],0.f);
            float m = a0; int am = 0;
            if (a1 > m) { m = a1; am = 1; }
            if (a2 > m) { m = a2; am = 2; }
            if (a3 > m) { m = a3; am = 3; }
            size_t ob = ((size_t)(n*64+oc0+o)*Hp + py)*Wp + tx;
            p[ob] = m;
            idx[ob] = (m > 0.f) ? (unsigned char)am : (unsigned char)4;
        }
    }
}

// smem-staged backward-data conv3x3 with FUSED unpool input synthesis:
// input delta[y,x] = (ib[pool cell]==quadrant) ? dp[pool cell] : 0
__launch_bounds__(128)
__global__ void convbwd_sm_k(const float* __restrict__ dp, const unsigned char* __restrict__ ib,
                             const float* __restrict__ wt, float* __restrict__ out,
                             int H, int W, int TR)
{
    const int n = blockIdx.z, oc0 = blockIdx.y*8, tr0 = blockIdx.x*TR;
    const int W2 = W + 2;
    const int BUFN = (2*TR+2)*W2;
    const int TH = (H+1)>>1, TW = (W+1)>>1;
    const int Hp = H>>1, Wp = W>>1;
    __shared__ float ws[8*64*12];
    extern __shared__ float buf[];
    const int tid = threadIdx.x;
    for (int i = tid; i < 8*64*9; i += 128) {
        int oi = i/9, k = i - oi*9;
        ws[oi*12+k] = wt[(size_t)oc0*64*9 + i];
    }
    const int y_lo = 2*tr0 - 1;
    auto fill = [&](float* b, int ic) {
        const size_t pb = (size_t)(n*64+ic)*Hp*Wp;
        for (int i = tid; i < BUFN; i += 128) {
            int r = i / W2, c = i - r*W2;
            int y = y_lo + r, x = c - 1;
            float v = 0.f;
            if ((unsigned)y < (unsigned)(2*Hp) && (unsigned)x < (unsigned)(2*Wp)) {
                int py = y>>1, px = x>>1, j = ((y&1)<<1)|(x&1);
                size_t pi = pb + py*Wp + px;
                if (ib[pi] == j) v = dp[pi];
            }
            b[i] = v;
        }
    };
    fill(buf, 0);
    const int lt = tid, tyl = lt / TW, tx = lt - tyl*TW;
    const bool act = (lt < TR*TW) && (tr0 + tyl < TH);
    __syncthreads();
    float acc[8][4];
    #pragma unroll
    for (int o = 0; o < 8; o++) { acc[o][0]=0.f; acc[o][1]=0.f; acc[o][2]=0.f; acc[o][3]=0.f; }
    #pragma unroll 1
    for (int ic = 0; ic < 64; ic++) {
        const float* cb = buf + (ic & 1)*BUFN;
        if (ic + 1 < 64) fill(buf + ((ic+1) & 1)*BUFN, ic+1);
        if (act) {
            float v[4][4];
            #pragma unroll
            for (int u = 0; u < 4; u++)
            #pragma unroll
            for (int j = 0; j < 4; j++)
                v[u][j] = cb[(2*tyl+u)*W2 + 2*tx + j];
            #pragma unroll
            for (int o = 0; o < 8; o++) {
                float wr[12];
                *(float4*)&wr[0] = *(const float4*)&ws[(o*64+ic)*12];
                *(float4*)&wr[4] = *(const float4*)&ws[(o*64+ic)*12+4];
                wr[8] = ws[(o*64+ic)*12+8];
                #pragma unroll
                for (int u = 0; u < 3; u++)
                #pragma unroll
                for (int vv = 0; vv < 3; vv++) {
                    float wv = wr[u*3+vv];
                    acc[o][0] += wv*v[u  ][vv  ];
                    acc[o][1] += wv*v[u  ][vv+1];
                    acc[o][2] += wv*v[u+1][vv  ];
                    acc[o][3] += wv*v[u+1][vv+1];
                }
            }
        }
        __syncthreads();
    }
    if (act) {
        const int y0 = 2*(tr0 + tyl), x0 = 2*tx;
        const bool xv = (x0+1 < W), yv = (y0+1 < H);
        #pragma unroll
        for (int o = 0; o < 8; o++) {
            float* op = out + ((size_t)(n*64+oc0+o)*H + y0)*W + x0;
            op[0] = acc[o][0];
            if (xv) op[1] = acc[o][1];
            if (yv) { op[W] = acc[o][2]; if (xv) op[W+1] = acc[o][3]; }
        }
    }
}

// old register conv for the tiny 10x10 layers (5 images per block)
template<int IC, int NPB, int PXT>
__launch_bounds__(128)
__global__ void convpool_k(const float* __restrict__ in, const float* __restrict__ w,
                           const float* __restrict__ bias, float* __restrict__ p,
                           unsigned char* __restrict__ idx,
                           int H, int W, int Hp, int Wp)
{
    const int oc0 = blockIdx.y*8;
    __shared__ float ws[8*IC*12];
    __shared__ float bs[8];
    for (int i = threadIdx.x; i < 8*IC*9; i += 128) {
        int oi = i/9, k = i - oi*9;
        ws[oi*12+k] = w[(size_t)oc0*IC*9 + i];
    }
    if (threadIdx.x < 8) bs[threadIdx.x] = bias[oc0+threadIdx.x];
    __syncthreads();
    int q = threadIdx.x / PXT, t = threadIdx.x - q*PXT;
    int n = blockIdx.z*NPB + q;
    if (q >= NPB || n >= 128) return;
    int py = t / Wp, px = t - py*Wp;
    int y0 = py*2, x0 = px*2;
    int offs[4][4];
    #pragma unroll
    for (int u = 0; u < 4; u++) {
        int yy = y0-1+u; bool rv = (unsigned)yy < (unsigned)H;
        #pragma unroll
        for (int j = 0; j < 4; j++) {
            int xx = x0-1+j;
            offs[u][j] = (rv && (unsigned)xx < (unsigned)W) ? yy*W+xx : -1;
        }
    }
    float acc[8][4];
    #pragma unroll
    for (int o = 0; o < 8; o++) {
        float b = bs[o];
        acc[o][0]=b; acc[o][1]=b; acc[o][2]=b; acc[o][3]=b;
    }
    const float* ip = in + (size_t)n*IC*H*W;
    #pragma unroll 1
    for (int ic = 0; ic < IC; ic++, ip += H*W) {
        float v[4][4];
        #pragma unroll
        for (int u = 0; u < 4; u++)
        #pragma unroll
        for (int j = 0; j < 4; j++)
            v[u][j] = (offs[u][j] >= 0) ? ip[offs[u][j]] : 0.0f;
        #pragma unroll
        for (int o = 0; o < 8; o++) {
            float wr[12];
            *(float4*)&wr[0] = *(const float4*)&ws[(o*IC+ic)*12];
            *(float4*)&wr[4] = *(const float4*)&ws[(o*IC+ic)*12+4];
            wr[8] = ws[(o*IC+ic)*12+8];
            #pragma unroll
            for (int u = 0; u < 3; u++)
            #pragma unroll
            for (int vv = 0; vv < 3; vv++) {
                float wv = wr[u*3+vv];
                acc[o][0] += wv*v[u  ][vv  ];
                acc[o][1] += wv*v[u  ][vv+1];
                acc[o][2] += wv*v[u+1][vv  ];
                acc[o][3] += wv*v[u+1][vv+1];
            }
        }
    }
    #pragma unroll
    for (int o = 0; o < 8; o++) {
        float a0 = fmaxf(acc[o][0],0.f), a1 = fmaxf(acc[o][1],0.f),
              a2 = fmaxf(acc[o][2],0.f), a3 = fmaxf(acc[o][3],0.f);
        float m = a0; int am = 0;
        if (a1 > m) { m = a1; am = 1; }
        if (a2 > m) { m = a2; am = 2; }
        if (a3 > m) { m = a3; am = 3; }
        size_t ob = ((size_t)(n*64+oc0+o)*Hp + py)*Wp + px;
        p[ob] = m;
        idx[ob] = (m > 0.f) ? (unsigned char)am : (unsigned char)4;
    }
}

template<int IC, int NPB, int PXT>
__launch_bounds__(128)
__global__ void conv2_k(const float* __restrict__ in, const float* __restrict__ w,
                        float* __restrict__ out, int H, int W)
{
    const int n0 = blockIdx.z, oc0 = blockIdx.y*8;
    const int TW = (W+1) >> 1;
    __shared__ float ws[8*IC*12];
    for (int i = threadIdx.x; i < 8*IC*9; i += 128) {
        int oi = i/9, k = i - oi*9;
        ws[oi*12+k] = w[(size_t)oc0*IC*9 + i];
    }
    __syncthreads();
    int q = threadIdx.x / PXT, t = threadIdx.x - q*PXT;
    int n = n0*NPB + q;
    if (q >= NPB || n >= 128) return;
    int ty = t / TW, tx = t - ty*TW;
    int y0 = ty*2, x0 = tx*2;
    int offs[4][4];
    #pragma unroll
    for (int u = 0; u < 4; u++) {
        int yy = y0-1+u; bool rv = (unsigned)yy < (unsigned)H;
        #pragma unroll
        for (int j = 0; j < 4; j++) {
            int xx = x0-1+j;
            offs[u][j] = (rv && (unsigned)xx < (unsigned)W) ? yy*W+xx : -1;
        }
    }
    float acc[8][4];
    #pragma unroll
    for (int o = 0; o < 8; o++) { acc[o][0]=0.f; acc[o][1]=0.f; acc[o][2]=0.f; acc[o][3]=0.f; }
    const float* ip = in + (size_t)n*IC*H*W;
    #pragma unroll 1
    for (int ic = 0; ic < IC; ic++, ip += H*W) {
        float v[4][4];
        #pragma unroll
        for (int u = 0; u < 4; u++)
        #pragma unroll
        for (int j = 0; j < 4; j++)
            v[u][j] = (offs[u][j] >= 0) ? ip[offs[u][j]] : 0.0f;
        #pragma unroll
        for (int o = 0; o < 8; o++) {
            float wr[12];
            *(float4*)&wr[0] = *(const float4*)&ws[(o*IC+ic)*12];
            *(float4*)&wr[4] = *(const float4*)&ws[(o*IC+ic)*12+4];
            wr[8] = ws[(o*IC+ic)*12+8];
            #pragma unroll
            for (int u = 0; u < 3; u++)
            #pragma unroll
            for (int vv = 0; vv < 3; vv++) {
                float wv = wr[u*3+vv];
                acc[o][0] += wv*v[u  ][vv  ];
                acc[o][1] += wv*v[u  ][vv+1];
                acc[o][2] += wv*v[u+1][vv  ];
                acc[o][3] += wv*v[u+1][vv+1];
            }
        }
    }
    bool xv = (x0+1 < W), yv = (y0+1 < H);
    #pragma unroll
    for (int o = 0; o < 8; o++) {
        float* op = out + ((size_t)(n*64+oc0+o)*H + y0)*W + x0;
        op[0] = acc[o][0];
        if (xv) op[1] = acc[o][1];
        if (yv) { op[W] = acc[o][2]; if (xv) op[W+1] = acc[o][3]; }
    }
}

__global__ void unpool_fc_k(const float* __restrict__ fcw, const int* __restrict__ cptr,
                            const unsigned char* __restrict__ idx, float* __restrict__ delta)
{
    int t = blockIdx.x*256 + threadIdx.x;
    if (t >= 128*64*100) return;
    int x = t % 10, y = (t / 10) % 10, ch = (t / 100) % 64, n = t / 6400;
    int py = y >> 1, px = x >> 1, j = ((y & 1) << 1) | (x & 1);
    int pi = ((n*64 + ch)*5 + py)*5 + px;
    float val = 0.0f;
    if (idx[pi] == j) {
        int cc = cptr[0];
        val = fcw[cc*1600 + ch*25 + py*5 + px];
    }
    delta[t] = val;
}

__global__ void transw_k(const float* __restrict__ w, float* __restrict__ wt) {
    int t = blockIdx.x*256 + threadIdx.x;
    if (t >= 64*64*9) return;
    int uv = t % 9, ic = (t / 9) % 64, oc = t / 576;
    int u = uv / 3, v = uv % 3;
    wt[(ic*64 + oc)*9 + (2-u)*3 + (2-v)] = w[t];
}

// weight+bias gradient, layers 1..3, packed f32x2 over oc-pairs.
// delta synthesized from (dp, ib) when ib != nullptr (fused unpool).
template<int IC, int ICC>
__global__ void wgrad2_k(const float* __restrict__ dp, const unsigned char* __restrict__ ib,
                         const float* __restrict__ in,
                         float* __restrict__ G, int gofs, int bofs,
                         const float* __restrict__ scal, int sidx, int H, int W,
                         int Hp, int Wp)
{
    const int n = blockIdx.y, oc0 = blockIdx.x*4;
    const int DW = W | 1;
    const int PW = (W+2) | 1;
    const int PH = H + 2;
    const int HDW = H*DW, PHW = PH*PW;
    extern __shared__ float sm[];
    ull*   ds2  = (ull*)sm;
    float* ins  = sm + 4*HDW;
    float* bred = ins + ICC*PHW;
    const int tid = threadIdx.x;
    const int lane = tid & 31, icl = tid >> 5;
    const int NT = ICC*32;
    if (tid < 4) bred[tid] = 0.f;
    for (int i = tid; i < 2*HDW; i += NT) {
        int pr = i / HDW, r = i - pr*HDW;
        int y = r / DW, x = r - y*DW;
        float lo = 0.f, hi = 0.f;
        if (x < W) {
            int plane0 = n*64 + oc0 + 2*pr;
            if (ib) {
                if (y < 2*Hp && x < 2*Wp) {
                    int py = y>>1, px = x>>1, j = ((y&1)<<1)|(x&1);
                    size_t pi0 = ((size_t)plane0*Hp + py)*Wp + px;
                    size_t pi1 = pi0 + (size_t)Hp*Wp;
                    if (ib[pi0] == j) lo = dp[pi0];
                    if (ib[pi1] == j) hi = dp[pi1];
                }
            } else {
                size_t b = (size_t)plane0*H*W + y*W + x;
                lo = dp[b]; hi = dp[b + (size_t)H*W];
            }
        }
        ds2[i] = pk(lo, hi);
    }
    __syncthreads();
    #pragma unroll
    for (int pr = 0; pr < 2; pr++) {
        float s0 = 0.f, s1 = 0.f;
        for (int i = tid; i < HDW; i += NT) {
            float lo, hi; upk(ds2[pr*HDW + i], lo, hi);
            s0 += lo; s1 += hi;
        }
        #pragma unroll
        for (int off = 16; off; off >>= 1) {
            s0 += __shfl_xor_sync(0xffffffffu, s0, off);
            s1 += __shfl_xor_sync(0xffffffffu, s1, off);
        }
        if (lane == 0) { atomicAdd(&bred[2*pr], s0); atomicAdd(&bred[2*pr+1], s1); }
    }
    const float s  = scal[sidx];
    const float sb = scal[sidx+1];
    for (int chunk = 0; chunk < IC; chunk += ICC) {
        __syncthreads();
        for (int i = tid; i < ICC*PHW; i += NT) {
            int icp = i / PHW, r = i - icp*PHW;
            int yy = r / PW - 1, xx = r - (yy+1)*PW - 1;
            float val = 0.f;
            if ((unsigned)yy < (unsigned)H && (unsigned)xx < (unsigned)W)
                val = in[(size_t)(n*IC + chunk + icp)*H*W + yy*W + xx];
            ins[i] = val;
        }
        __syncthreads();
        ull acc[2][9];
        #pragma unroll
        for (int pr = 0; pr < 2; pr++)
        #pragma unroll
        for (int k = 0; k < 9; k++) acc[pr][k] = 0ull;
        const float* myin = ins + icl*PHW;
        for (int y = lane; y < H; y += 32) {
            const float* r0p = myin + y*PW;
            const float* r1p = r0p + PW;
            const float* r2p = r1p + PW;
            const ull* d0y = ds2 + y*DW;
            const ull* d1y = ds2 + HDW + y*DW;
            float f;
            f = r0p[0]; ull pa0 = pk(f,f);
            f = r0p[1]; ull pa1 = pk(f,f);
            f = r1p[0]; ull pb0 = pk(f,f);
            f = r1p[1]; ull pb1 = pk(f,f);
            f = r2p[0]; ull pc0 = pk(f,f);
            f = r2p[1]; ull pc1 = pk(f,f);
            #pragma unroll 2
            for (int x = 0; x < W; x++) {
                float na = r0p[x+2], nb = r1p[x+2], nc = r2p[x+2];
                ull pa2 = pk(na,na), pb2 = pk(nb,nb), pc2 = pk(nc,nc);
                ull d0 = d0y[x], d1 = d1y[x];
                ffma2(acc[0][0], d0, pa0); ffma2(acc[0][1], d0, pa1); ffma2(acc[0][2], d0, pa2);
                ffma2(acc[0][3], d0, pb0); ffma2(acc[0][4], d0, pb1); ffma2(acc[0][5], d0, pb2);
                ffma2(acc[0][6], d0, pc0); ffma2(acc[0][7], d0, pc1); ffma2(acc[0][8], d0, pc2);
                ffma2(acc[1][0], d1, pa0); ffma2(acc[1][1], d1, pa1); ffma2(acc[1][2], d1, pa2);
                ffma2(acc[1][3], d1, pb0); ffma2(acc[1][4], d1, pb1); ffma2(acc[1][5], d1, pb2);
                ffma2(acc[1][6], d1, pc0); ffma2(acc[1][7], d1, pc1); ffma2(acc[1][8], d1, pc2);
                pa0 = pa1; pa1 = pa2; pb0 = pb1; pb1 = pb2; pc0 = pc1; pc1 = pc2;
            }
        }
        #pragma unroll
        for (int pr = 0; pr < 2; pr++)
        #pragma unroll
        for (int k = 0; k < 9; k++) {
            float v0, v1; upk(acc[pr][k], v0, v1);
            #pragma unroll
            for (int off = 16; off; off >>= 1) {
                v0 += __shfl_xor_sync(0xffffffffu, v0, off);
                v1 += __shfl_xor_sync(0xffffffffu, v1, off);
            }
            if (lane == 0) {
                size_t base = (size_t)n*F + gofs;
                G[base + ((size_t)(oc0+2*pr  )*IC + chunk + icl)*9 + k] = s*v0;
                G[base + ((size_t)(oc0+2*pr+1)*IC + chunk + icl)*9 + k] = s*v1;
            }
        }
    }
    __syncthreads();
    if (tid < 4) G[(size_t)n*F + bofs + oc0 + tid] = sb*bred[tid];
}

// layer-0 weight+bias gradient with fused unpool (no d0 buffer)
__global__ void wgrad0_k(const float* __restrict__ dp0, const unsigned char* __restrict__ i0,
                         const float* __restrict__ xp, float* __restrict__ G,
                         const float* __restrict__ scal)
{
    const int n = blockIdx.y, oh = blockIdx.x;
    extern __shared__ float sm[];
    float* ins  = sm;                 // 3*86*87
    float* ds   = ins + 22446;        // 84*85
    float* red  = ds + 7140;          // 3*9*84
    float* bred = red + 2268;         // 8
    const int tid = threadIdx.x;      // 256
    for (int i = tid; i < 3*86*87; i += 256) {
        int icp = i/(86*87), r = i - icp*(86*87);
        int yy = r/87 - 1, xx = r - (yy+1)*87 - 1;
        float val = 0.f;
        if ((unsigned)yy < 84u && (unsigned)xx < 84u)
            val = xp[(size_t)(n*3+icp)*7056 + yy*84 + xx];
        ins[i] = val;
    }
    const float s = scal[0], sb = scal[1];
    const int icl = tid / 84, rg = tid - icl*84;
    for (int oc8 = 0; oc8 < 32; oc8++) {
        const int oc = oh*32 + oc8;
        __syncthreads();
        const float* dpp = dp0 + (size_t)(n*64+oc)*1764;
        const unsigned char* ipp = i0 + (size_t)(n*64+oc)*1764;
        for (int i = tid; i < 84*85; i += 256) {
            int y = i/85, x = i - y*85;
            float val = 0.f;
            if (x < 84) {
                int py = y>>1, px = x>>1, j = ((y&1)<<1)|(x&1);
                int pi = py*42 + px;
                if (ipp[pi] == j) val = dpp[pi];
            }
            ds[i] = val;
        }
        __syncthreads();
        float bp = 0.f;
        for (int i = tid; i < 84*85; i += 256) bp += ds[i];
        #pragma unroll
        for (int off = 16; off; off >>= 1) bp += __shfl_xor_sync(0xffffffffu, bp, off);
        if ((tid & 31) == 0) bred[tid >> 5] = bp;
        float acc[9];
        #pragma unroll
        for (int k = 0; k < 9; k++) acc[k] = 0.f;
        if (tid < 252) {
            const float* r0p = ins + icl*7482 + rg*87;
            const float* r1p = r0p + 87;
            const float* r2p = r1p + 87;
            const float* dsy = ds + rg*85;
            float a0=r0p[0],a1=r0p[1],b0=r1p[0],b1=r1p[1],c0=r2p[0],c1=r2p[1];
            #pragma unroll 2
            for (int x = 0; x < 84; x++) {
                float a2=r0p[x+2], b2=r1p[x+2], c2=r2p[x+2];
                float d = dsy[x];
                acc[0]+=d*a0; acc[1]+=d*a1; acc[2]+=d*a2;
                acc[3]+=d*b0; acc[4]+=d*b1; acc[5]+=d*b2;
                acc[6]+=d*c0; acc[7]+=d*c1; acc[8]+=d*c2;
                a0=a1;a1=a2;b0=b1;b1=b2;c0=c1;c1=c2;
            }
            #pragma unroll
            for (int k = 0; k < 9; k++) red[(icl*9+k)*84 + rg] = acc[k];
        }
        __syncthreads();
        if (tid == 0) {
            float a = 0.f;
            #pragma unroll
            for (int wq = 0; wq < 8; wq++) a += bred[wq];
            G[(size_t)n*F + OB0 + oc] = sb*a;
        }
        for (int o = tid; o < 27; o += 256) {
            float t2 = 0.f;
            for (int r = 0; r < 84; r++) t2 += red[o*84 + r];
            int icg = o/9, uv = o - icg*9;
            G[(size_t)n*F + OW0 + (oc*3 + icg)*9 + uv] = s*t2;
        }
    }
}

__global__ void copyp3_k(const float* __restrict__ p3, float* __restrict__ G,
                         const float* __restrict__ scal)
{
    int t = blockIdx.x*256 + threadIdx.x;
    if (t >= 128*1600) return;
    int n = t / 1600, j = t - n*1600;
    G[(size_t)n*F + OFC + j] = scal[8]*p3[t];
}

__global__ void gemm_part_k(const float* __restrict__ G, float* __restrict__ part)
{
    const int ty = threadIdx.y, tx = threadIdx.x;
    const int bn = blockIdx.y*16, bm = blockIdx.x*16, sp = blockIdx.z;
    __shared__ float A[16][65], B[16][65];
    const int f0 = sp*(F/8);
    const int tid = ty*16 + tx, row = tid >> 4, q = tid & 15;
    float acc = 0.0f;
    for (int f = f0; f < f0 + F/8; f += 64) {
        float4 a4 = *(const float4*)(G + (size_t)(bn + row)*F + f + q*4);
        float4 b4 = *(const float4*)(G + (size_t)(64 + bm + row)*F + f + q*4);
        A[row][q*4+0] = a4.x; A[row][q*4+1] = a4.y; A[row][q*4+2] = a4.z; A[row][q*4+3] = a4.w;
        B[row][q*4+0] = b4.x; B[row][q*4+1] = b4.y; B[row][q*4+2] = b4.z; B[row][q*4+3] = b4.w;
        __syncthreads();
        #pragma unroll
        for (int k = 0; k < 64; k++) acc += A[ty][k]*B[tx][k];
        __syncthreads();
    }
    part[sp*4096 + (bn + ty)*64 + (bm + tx)] = acc;
}

__global__ void reduce_k(const float* __restrict__ part, const float* __restrict__ scal,
                         float* __restrict__ out)
{
    int t = blockIdx.x*256 + threadIdx.x;
    if (t >= 4096) return;
    float a = scal[9]*scal[9];
    #pragma unroll
    for (int sp = 0; sp < 8; sp++) a += part[sp*4096 + t];
    out[t] = a;
}

// ---------------- host ----------------
extern "C" void kernel_launch(void* const* d_in, const int* in_sizes, int n_in,
                              void* d_out, int out_size)
{
    const float* x1  = (const float*)d_in[0];
    const float* x2  = (const float*)d_in[1];
    const float* scal= (const float*)d_in[2];
    const int*   cp  = (const int*)  d_in[3];
    const float* w0  = (const float*)d_in[4];
    const float* b0  = (const float*)d_in[5];
    const float* w1  = (const float*)d_in[6];
    const float* b1  = (const float*)d_in[7];
    const float* w2  = (const float*)d_in[8];
    const float* b2  = (const float*)d_in[9];
    const float* w3  = (const float*)d_in[10];
    const float* b3  = (const float*)d_in[11];
    const float* fcw = (const float*)d_in[12];
    float* out = (float*)d_out;

    float *xp,*p0,*dp0,*p1,*dp1,*p2,*d3,*dp2,*p3,*wt,*G,*part;
    unsigned char *i0,*i1,*i2,*i3;
    cudaGetSymbolAddress((void**)&xp,  g_x);
    cudaGetSymbolAddress((void**)&p0,  g_p0);
    cudaGetSymbolAddress((void**)&dp0, g_dp0);
    cudaGetSymbolAddress((void**)&i0,  g_i0);
    cudaGetSymbolAddress((void**)&p1,  g_p1);
    cudaGetSymbolAddress((void**)&dp1, g_dp1);
    cudaGetSymbolAddress((void**)&i1,  g_i1);
    cudaGetSymbolAddress((void**)&p2,  g_p2);
    cudaGetSymbolAddress((void**)&d3,  g_d3);
    cudaGetSymbolAddress((void**)&dp2, g_dp2);
    cudaGetSymbolAddress((void**)&i2,  g_i2);
    cudaGetSymbolAddress((void**)&p3,  g_p3);
    cudaGetSymbolAddress((void**)&i3,  g_i3);
    cudaGetSymbolAddress((void**)&wt,  g_wt);
    cudaGetSymbolAddress((void**)&G,   g_G);
    cudaGetSymbolAddress((void**)&part,g_part);

    const int smW0 = (22446 + 7140 + 2268 + 8)*4;
    const int sm42 = (4*42*43)*4 + (8*44*45)*4 + 16;
    const int sm21 = (4*21*21)*4 + (8*23*23)*4 + 16;
    const int sm10 = (4*10*11)*4 + (8*12*13)*4 + 16;

    // dynamic smem for staged convs: 2 * (2*TR+2)*(W+2) floats
    const int dynF84 = 2*(8 *86)*4;   // TR=3
    const int dynF42 = 2*(14*44)*4;   // TR=6
    const int dynF21 = 2*(22*23)*4;   // TR=10
    const int dynB42 = 2*(14*44)*4;   // TR=6
    const int dynB21 = 2*(24*23)*4;   // TR=11

    static bool init = false;
    if (!init) {
        init = true;
        cudaFuncSetAttribute(wgrad0_k, cudaFuncAttributeMaxDynamicSharedMemorySize, smW0);
        cudaFuncSetAttribute(wgrad2_k<64,8>, cudaFuncAttributeMaxDynamicSharedMemorySize, sm42);
    }

    // ---- forward (smem-staged conv+relu+pool fused) ----
    pack_x_k<<<(128*3*84*84 + 255)/256, 256>>>(x1, x2, xp);
    convpool_sm_k<3> <<<dim3(14,8,128),128,dynF84>>>(xp, w0, b0, p0, i0, 84, 84, 42, 42, 3);
    convpool_sm_k<64><<<dim3(4, 8,128),128,dynF42>>>(p0, w1, b1, p1, i1, 42, 42, 21, 21, 6);
    convpool_sm_k<64><<<dim3(1, 8,128),128,dynF21>>>(p1, w2, b2, p2, i2, 21, 21, 10, 10, 10);
    convpool_k<64,5,25><<<dim3(1,8,26),128>>>(p2, w3, b3, p3, i3, 10, 10, 5, 5);

    // ---- backward (scalar output c); unpool fused into consumers ----
    unpool_fc_k<<<(128*64*100 + 255)/256, 256>>>(fcw, cp, i3, d3);
    transw_k<<<144,256>>>(w3, wt + 0*WTS);
    transw_k<<<144,256>>>(w2, wt + 1*WTS);
    transw_k<<<144,256>>>(w1, wt + 2*WTS);
    conv2_k<64,5,25><<<dim3(1,8,26),128>>>(d3, wt + 0*WTS, dp2, 10, 10);
    convbwd_sm_k<<<dim3(1,8,128),128,dynB21>>>(dp2, i2, wt + 1*WTS, dp1, 21, 21, 11);
    convbwd_sm_k<<<dim3(4,8,128),128,dynB42>>>(dp1, i1, wt + 2*WTS, dp0, 42, 42, 6);

    // ---- per-example gradients -> scaled feature matrix G ----
    wgrad0_k<<<dim3(2,128), 256, smW0>>>(dp0, i0, xp, G, scal);
    wgrad2_k<64,8><<<dim3(16,128), 256, sm42>>>(dp1, i1, p0, G, OW1, OB1, scal, 2, 42, 42, 21, 21);
    wgrad2_k<64,8><<<dim3(16,128), 256, sm21>>>(dp2, i2, p1, G, OW2, OB2, scal, 4, 21, 21, 10, 10);
    wgrad2_k<64,8><<<dim3(16,128), 256, sm10>>>(d3, nullptr, p2, G, OW3, OB3, scal, 6, 10, 10, 5, 5);
    copyp3_k<<<(128*1600 + 255)/256, 256>>>(p3, G, scal);

    // ---- K = G1 G2^T + s_fcb^2 ----
    gemm_part_k<<<dim3(4,4,8), dim3(16,16)>>>(G, part);
    reduce_k<<<16,256>>>(part, scal, out);
}

// round 7
// speedup vs baseline: 1.1525x; 1.1525x over previous
#include <cuda_runtime.h>

typedef unsigned long long ull;

__device__ __forceinline__ ull pk(float lo, float hi) {
    ull r; asm("mov.b64 %0,{%1,%2};" : "=l"(r) : "f"(lo), "f"(hi)); return r;
}
__device__ __forceinline__ void upk(ull v, float& lo, float& hi) {
    asm("mov.b64 {%0,%1},%2;" : "=f"(lo), "=f"(hi) : "l"(v));
}
__device__ __forceinline__ void ffma2(ull& d, ull a, ull b) {
    asm("fma.rn.f32x2 %0,%1,%2,%0;" : "+l"(d) : "l"(a), "l"(b));
}

// ---------------- constants ----------------
constexpr int F = 114176;
constexpr int OW0 = 0, OB0 = 1728, OW1 = 1792, OB1 = 38656, OW2 = 38720,
              OB2 = 75584, OW3 = 75648, OB3 = 112512, OFC = 112576;
constexpr int WTS = 64*64*9;

// ---------------- scratch ----------------
__device__ float g_x  [128*3*84*84];
__device__ float g_p0 [128*64*42*42];
__device__ float g_dp0[128*64*42*42];
__device__ unsigned char g_i0[128*64*42*42];
__device__ float g_p1 [128*64*21*21];
__device__ float g_dp1[128*64*21*21];
__device__ unsigned char g_i1[128*64*21*21];
__device__ float g_p2 [128*64*10*10];
__device__ float g_d3 [128*64*10*10];
__device__ float g_dp2[128*64*10*10];
__device__ unsigned char g_i2[128*64*10*10];
__device__ float g_p3 [128*64*5*5];
__device__ unsigned char g_i3[128*64*5*5];
__device__ float g_wt [3*WTS];
__device__ float g_G  [128*(size_t)F];
__device__ float g_part[8*4096];

// ---------------- kernels ----------------
__global__ void pack_x_k(const float* __restrict__ x1, const float* __restrict__ x2,
                         float* __restrict__ xo) {
    int t = blockIdx.x*256 + threadIdx.x;
    const int P = 3*84*84;
    if (t >= 128*P) return;
    int n = t / P, k = t - n*P;
    xo[t] = (n < 64) ? x1[n*P + k] : x2[(n-64)*P + k];
}

// fused conv3x3(SAME)+bias+relu+2x2 maxpool; register tiles (R4-proven form)
template<int IC, int NPB, int PXT>
__launch_bounds__(128)
__global__ void convpool_k(const float* __restrict__ in, const float* __restrict__ w,
                           const float* __restrict__ bias, float* __restrict__ p,
                           unsigned char* __restrict__ idx,
                           int H, int W, int Hp, int Wp)
{
    const int oc0 = blockIdx.y*8;
    __shared__ float ws[8*IC*12];
    __shared__ float bs[8];
    for (int i = threadIdx.x; i < 8*IC*9; i += 128) {
        int oi = i/9, k = i - oi*9;
        ws[oi*12+k] = w[(size_t)oc0*IC*9 + i];
    }
    if (threadIdx.x < 8) bs[threadIdx.x] = bias[oc0+threadIdx.x];
    __syncthreads();
    int n, t;
    if (NPB == 1) {
        n = blockIdx.z; t = blockIdx.x*128 + threadIdx.x;
        if (t >= Hp*Wp) return;
    } else {
        int q = threadIdx.x / PXT; t = threadIdx.x - q*PXT;
        n = blockIdx.z*NPB + q;
        if (q >= NPB || n >= 128) return;
    }
    int py = t / Wp, px = t - py*Wp;
    int y0 = py*2, x0 = px*2;
    int offs[4][4];
    #pragma unroll
    for (int u = 0; u < 4; u++) {
        int yy = y0-1+u; bool rv = (unsigned)yy < (unsigned)H;
        #pragma unroll
        for (int j = 0; j < 4; j++) {
            int xx = x0-1+j;
            offs[u][j] = (rv && (unsigned)xx < (unsigned)W) ? yy*W+xx : -1;
        }
    }
    float acc[8][4];
    #pragma unroll
    for (int o = 0; o < 8; o++) {
        float b = bs[o];
        acc[o][0]=b; acc[o][1]=b; acc[o][2]=b; acc[o][3]=b;
    }
    const float* ip = in + (size_t)n*IC*H*W;
    #pragma unroll 1
    for (int ic = 0; ic < IC; ic++, ip += H*W) {
        float v[4][4];
        #pragma unroll
        for (int u = 0; u < 4; u++)
        #pragma unroll
        for (int j = 0; j < 4; j++)
            v[u][j] = (offs[u][j] >= 0) ? ip[offs[u][j]] : 0.0f;
        #pragma unroll
        for (int o = 0; o < 8; o++) {
            float wr[12];
            *(float4*)&wr[0] = *(const float4*)&ws[(o*IC+ic)*12];
            *(float4*)&wr[4] = *(const float4*)&ws[(o*IC+ic)*12+4];
            wr[8] = ws[(o*IC+ic)*12+8];
            #pragma unroll
            for (int u = 0; u < 3; u++)
            #pragma unroll
            for (int vv = 0; vv < 3; vv++) {
                float wv = wr[u*3+vv];
                acc[o][0] += wv*v[u  ][vv  ];
                acc[o][1] += wv*v[u  ][vv+1];
                acc[o][2] += wv*v[u+1][vv  ];
                acc[o][3] += wv*v[u+1][vv+1];
            }
        }
    }
    #pragma unroll
    for (int o = 0; o < 8; o++) {
        float a0 = fmaxf(acc[o][0],0.f), a1 = fmaxf(acc[o][1],0.f),
              a2 = fmaxf(acc[o][2],0.f), a3 = fmaxf(acc[o][3],0.f);
        float m = a0; int am = 0;
        if (a1 > m) { m = a1; am = 1; }
        if (a2 > m) { m = a2; am = 2; }
        if (a3 > m) { m = a3; am = 3; }
        size_t ob = ((size_t)(n*64+oc0+o)*Hp + py)*Wp + px;
        p[ob] = m;
        idx[ob] = (m > 0.f) ? (unsigned char)am : (unsigned char)4;
    }
}

// plain backward-data conv reading a full-res delta buffer (10x10 layer only)
template<int IC, int NPB, int PXT>
__launch_bounds__(128)
__global__ void conv2_k(const float* __restrict__ in, const float* __restrict__ w,
                        float* __restrict__ out, int H, int W)
{
    const int n0 = blockIdx.z, oc0 = blockIdx.y*8;
    const int TW = (W+1) >> 1;
    __shared__ float ws[8*IC*12];
    for (int i = threadIdx.x; i < 8*IC*9; i += 128) {
        int oi = i/9, k = i - oi*9;
        ws[oi*12+k] = w[(size_t)oc0*IC*9 + i];
    }
    __syncthreads();
    int q = threadIdx.x / PXT, t = threadIdx.x - q*PXT;
    int n = n0*NPB + q;
    if (q >= NPB || n >= 128) return;
    int ty = t / TW, tx = t - ty*TW;
    int y0 = ty*2, x0 = tx*2;
    int offs[4][4];
    #pragma unroll
    for (int u = 0; u < 4; u++) {
        int yy = y0-1+u; bool rv = (unsigned)yy < (unsigned)H;
        #pragma unroll
        for (int j = 0; j < 4; j++) {
            int xx = x0-1+j;
            offs[u][j] = (rv && (unsigned)xx < (unsigned)W) ? yy*W+xx : -1;
        }
    }
    float acc[8][4];
    #pragma unroll
    for (int o = 0; o < 8; o++) { acc[o][0]=0.f; acc[o][1]=0.f; acc[o][2]=0.f; acc[o][3]=0.f; }
    const float* ip = in + (size_t)n*IC*H*W;
    #pragma unroll 1
    for (int ic = 0; ic < IC; ic++, ip += H*W) {
        float v[4][4];
        #pragma unroll
        for (int u = 0; u < 4; u++)
        #pragma unroll
        for (int j = 0; j < 4; j++)
            v[u][j] = (offs[u][j] >= 0) ? ip[offs[u][j]] : 0.0f;
        #pragma unroll
        for (int o = 0; o < 8; o++) {
            float wr[12];
            *(float4*)&wr[0] = *(const float4*)&ws[(o*IC+ic)*12];
            *(float4*)&wr[4] = *(const float4*)&ws[(o*IC+ic)*12+4];
            wr[8] = ws[(o*IC+ic)*12+8];
            #pragma unroll
            for (int u = 0; u < 3; u++)
            #pragma unroll
            for (int vv = 0; vv < 3; vv++) {
                float wv = wr[u*3+vv];
                acc[o][0] += wv*v[u  ][vv  ];
                acc[o][1] += wv*v[u  ][vv+1];
                acc[o][2] += wv*v[u+1][vv  ];
                acc[o][3] += wv*v[u+1][vv+1];
            }
        }
    }
    bool xv = (x0+1 < W), yv = (y0+1 < H);
    #pragma unroll
    for (int o = 0; o < 8; o++) {
        float* op = out + ((size_t)(n*64+oc0+o)*H + y0)*W + x0;
        op[0] = acc[o][0];
        if (xv) op[1] = acc[o][1];
        if (yv) { op[W] = acc[o][2]; if (xv) op[W+1] = acc[o][3]; }
    }
}

// backward-data conv with FUSED unpool: per ic, load 3x3 pool cells (dp + idx)
// and expand the 4x4 delta window via predicated selects.
__launch_bounds__(128)
__global__ void conv2f_k(const float* __restrict__ dp, const unsigned char* __restrict__ ib,
                         const float* __restrict__ w, float* __restrict__ out,
                         int H, int W, int Hp, int Wp)
{
    const int n = blockIdx.z, oc0 = blockIdx.y*8;
    const int TW = (W+1) >> 1, TH = (H+1) >> 1;
    __shared__ float ws[8*64*12];
    for (int i = threadIdx.x; i < 8*64*9; i += 128) {
        int oi = i/9, k = i - oi*9;
        ws[oi*12+k] = w[(size_t)oc0*64*9 + i];
    }
    __syncthreads();
    int t = blockIdx.x*128 + threadIdx.x;
    if (t >= TH*TW) return;
    int ty = t / TW, tx = t - ty*TW;
    // 3x3 pool-cell neighborhood offsets (+ validity)
    int poff[3][3];
    #pragma unroll
    for (int a = 0; a < 3; a++) {
        int py = ty - 1 + a; bool rv = (unsigned)py < (unsigned)Hp;
        #pragma unroll
        for (int b = 0; b < 3; b++) {
            int px = tx - 1 + b;
            poff[a][b] = (rv && (unsigned)px < (unsigned)Wp) ? py*Wp+px : -1;
        }
    }
    // window row u (y=2ty-1+u) -> pool row AY[u], quadrant row QY[u]; cols same
    const int AY[4] = {0,1,1,2};
    const int QY[4] = {1,0,1,0};
    float acc[8][4];
    #pragma unroll
    for (int o = 0; o < 8; o++) { acc[o][0]=0.f; acc[o][1]=0.f; acc[o][2]=0.f; acc[o][3]=0.f; }
    const int PS = Hp*Wp;
    const float* dpp = dp + (size_t)n*64*PS;
    const unsigned char* ibp = ib + (size_t)n*64*PS;
    #pragma unroll 1
    for (int ic = 0; ic < 64; ic++, dpp += PS, ibp += PS) {
        float d[3][3]; int id[3][3];
        #pragma unroll
        for (int a = 0; a < 3; a++)
        #pragma unroll
        for (int b = 0; b < 3; b++) {
            int o2 = poff[a][b];
            bool v2 = (o2 >= 0);
            d[a][b]  = v2 ? dpp[o2] : 0.f;
            id[a][b] = v2 ? (int)ibp[o2] : 4;
        }
        float v[4][4];
        #pragma unroll
        for (int u = 0; u < 4; u++)
        #pragma unroll
        for (int j = 0; j < 4; j++) {
            int a = AY[u], b = AY[j];
            int qq = QY[u]*2 + QY[j];
            v[u][j] = (id[a][b] == qq) ? d[a][b] : 0.f;
        }
        #pragma unroll
        for (int o = 0; o < 8; o++) {
            float wr[12];
            *(float4*)&wr[0] = *(const float4*)&ws[(o*64+ic)*12];
            *(float4*)&wr[4] = *(const float4*)&ws[(o*64+ic)*12+4];
            wr[8] = ws[(o*64+ic)*12+8];
            #pragma unroll
            for (int u = 0; u < 3; u++)
            #pragma unroll
            for (int vv = 0; vv < 3; vv++) {
                float wv = wr[u*3+vv];
                acc[o][0] += wv*v[u  ][vv  ];
                acc[o][1] += wv*v[u  ][vv+1];
                acc[o][2] += wv*v[u+1][vv  ];
                acc[o][3] += wv*v[u+1][vv+1];
            }
        }
    }
    int y0 = 2*ty, x0 = 2*tx;
    bool xv = (x0+1 < W), yv = (y0+1 < H);
    #pragma unroll
    for (int o = 0; o < 8; o++) {
        float* op = out + ((size_t)(n*64+oc0+o)*H + y0)*W + x0;
        op[0] = acc[o][0];
        if (xv) op[1] = acc[o][1];
        if (yv) { op[W] = acc[o][2]; if (xv) op[W+1] = acc[o][3]; }
    }
}

__global__ void unpool_fc_k(const float* __restrict__ fcw, const int* __restrict__ cptr,
                            const unsigned char* __restrict__ idx, float* __restrict__ delta)
{
    int t = blockIdx.x*256 + threadIdx.x;
    if (t >= 128*64*100) return;
    int x = t % 10, y = (t / 10) % 10, ch = (t / 100) % 64, n = t / 6400;
    int py = y >> 1, px = x >> 1, j = ((y & 1) << 1) | (x & 1);
    int pi = ((n*64 + ch)*5 + py)*5 + px;
    float val = 0.0f;
    if (idx[pi] == j) {
        int cc = cptr[0];
        val = fcw[cc*1600 + ch*25 + py*5 + px];
    }
    delta[t] = val;
}

__global__ void transw_k(const float* __restrict__ w, float* __restrict__ wt) {
    int t = blockIdx.x*256 + threadIdx.x;
    if (t >= 64*64*9) return;
    int uv = t % 9, ic = (t / 9) % 64, oc = t / 576;
    int u = uv / 3, v = uv % 3;
    wt[(ic*64 + oc)*9 + (2-u)*3 + (2-v)] = w[t];
}

// weight+bias gradient, layers 1..3, packed f32x2 over oc-pairs.
// delta synthesized from (dp, ib) when ib != nullptr (fused unpool).
template<int IC, int ICC>
__global__ void wgrad2_k(const float* __restrict__ dp, const unsigned char* __restrict__ ib,
                         const float* __restrict__ in,
                         float* __restrict__ G, int gofs, int bofs,
                         const float* __restrict__ scal, int sidx, int H, int W,
                         int Hp, int Wp)
{
    const int n = blockIdx.y, oc0 = blockIdx.x*4;
    const int DW = W | 1;
    const int PW = (W+2) | 1;
    const int PH = H + 2;
    const int HDW = H*DW, PHW = PH*PW;
    extern __shared__ float sm[];
    ull*   ds2  = (ull*)sm;
    float* ins  = sm + 4*HDW;
    float* bred = ins + ICC*PHW;
    const int tid = threadIdx.x;
    const int lane = tid & 31, icl = tid >> 5;
    const int NT = ICC*32;
    if (tid < 4) bred[tid] = 0.f;
    for (int i = tid; i < 2*HDW; i += NT) {
        int pr = i / HDW, r = i - pr*HDW;
        int y = r / DW, x = r - y*DW;
        float lo = 0.f, hi = 0.f;
        if (x < W) {
            int plane0 = n*64 + oc0 + 2*pr;
            if (ib) {
                if (y < 2*Hp && x < 2*Wp) {
                    int py = y>>1, px = x>>1, j = ((y&1)<<1)|(x&1);
                    size_t pi0 = ((size_t)plane0*Hp + py)*Wp + px;
                    size_t pi1 = pi0 + (size_t)Hp*Wp;
                    if (ib[pi0] == j) lo = dp[pi0];
                    if (ib[pi1] == j) hi = dp[pi1];
                }
            } else {
                size_t b = (size_t)plane0*H*W + y*W + x;
                lo = dp[b]; hi = dp[b + (size_t)H*W];
            }
        }
        ds2[i] = pk(lo, hi);
    }
    __syncthreads();
    #pragma unroll
    for (int pr = 0; pr < 2; pr++) {
        float s0 = 0.f, s1 = 0.f;
        for (int i = tid; i < HDW; i += NT) {
            float lo, hi; upk(ds2[pr*HDW + i], lo, hi);
            s0 += lo; s1 += hi;
        }
        #pragma unroll
        for (int off = 16; off; off >>= 1) {
            s0 += __shfl_xor_sync(0xffffffffu, s0, off);
            s1 += __shfl_xor_sync(0xffffffffu, s1, off);
        }
        if (lane == 0) { atomicAdd(&bred[2*pr], s0); atomicAdd(&bred[2*pr+1], s1); }
    }
    const float s  = scal[sidx];
    const float sb = scal[sidx+1];
    for (int chunk = 0; chunk < IC; chunk += ICC) {
        __syncthreads();
        for (int i = tid; i < ICC*PHW; i += NT) {
            int icp = i / PHW, r = i - icp*PHW;
            int yy = r / PW - 1, xx = r - (yy+1)*PW - 1;
            float val = 0.f;
            if ((unsigned)yy < (unsigned)H && (unsigned)xx < (unsigned)W)
                val = in[(size_t)(n*IC + chunk + icp)*H*W + yy*W + xx];
            ins[i] = val;
        }
        __syncthreads();
        ull acc[2][9];
        #pragma unroll
        for (int pr = 0; pr < 2; pr++)
        #pragma unroll
        for (int k = 0; k < 9; k++) acc[pr][k] = 0ull;
        const float* myin = ins + icl*PHW;
        for (int y = lane; y < H; y += 32) {
            const float* r0p = myin + y*PW;
            const float* r1p = r0p + PW;
            const float* r2p = r1p + PW;
            const ull* d0y = ds2 + y*DW;
            const ull* d1y = ds2 + HDW + y*DW;
            float f;
            f = r0p[0]; ull pa0 = pk(f,f);
            f = r0p[1]; ull pa1 = pk(f,f);
            f = r1p[0]; ull pb0 = pk(f,f);
            f = r1p[1]; ull pb1 = pk(f,f);
            f = r2p[0]; ull pc0 = pk(f,f);
            f = r2p[1]; ull pc1 = pk(f,f);
            #pragma unroll 2
            for (int x = 0; x < W; x++) {
                float na = r0p[x+2], nb = r1p[x+2], nc = r2p[x+2];
                ull pa2 = pk(na,na), pb2 = pk(nb,nb), pc2 = pk(nc,nc);
                ull d0 = d0y[x], d1 = d1y[x];
                ffma2(acc[0][0], d0, pa0); ffma2(acc[0][1], d0, pa1); ffma2(acc[0][2], d0, pa2);
                ffma2(acc[0][3], d0, pb0); ffma2(acc[0][4], d0, pb1); ffma2(acc[0][5], d0, pb2);
                ffma2(acc[0][6], d0, pc0); ffma2(acc[0][7], d0, pc1); ffma2(acc[0][8], d0, pc2);
                ffma2(acc[1][0], d1, pa0); ffma2(acc[1][1], d1, pa1); ffma2(acc[1][2], d1, pa2);
                ffma2(acc[1][3], d1, pb0); ffma2(acc[1][4], d1, pb1); ffma2(acc[1][5], d1, pb2);
                ffma2(acc[1][6], d1, pc0); ffma2(acc[1][7], d1, pc1); ffma2(acc[1][8], d1, pc2);
                pa0 = pa1; pa1 = pa2; pb0 = pb1; pb1 = pb2; pc0 = pc1; pc1 = pc2;
            }
        }
        #pragma unroll
        for (int pr = 0; pr < 2; pr++)
        #pragma unroll
        for (int k = 0; k < 9; k++) {
            float v0, v1; upk(acc[pr][k], v0, v1);
            #pragma unroll
            for (int off = 16; off; off >>= 1) {
                v0 += __shfl_xor_sync(0xffffffffu, v0, off);
                v1 += __shfl_xor_sync(0xffffffffu, v1, off);
            }
            if (lane == 0) {
                size_t base = (size_t)n*F + gofs;
                G[base + ((size_t)(oc0+2*pr  )*IC + chunk + icl)*9 + k] = s*v0;
                G[base + ((size_t)(oc0+2*pr+1)*IC + chunk + icl)*9 + k] = s*v1;
            }
        }
    }
    __syncthreads();
    if (tid < 4) G[(size_t)n*F + bofs + oc0 + tid] = sb*bred[tid];
}

// layer-0 weight+bias gradient with fused unpool (no d0 buffer)
__global__ void wgrad0_k(const float* __restrict__ dp0, const unsigned char* __restrict__ i0,
                         const float* __restrict__ xp, float* __restrict__ G,
                         const float* __restrict__ scal)
{
    const int n = blockIdx.y, oh = blockIdx.x;
    extern __shared__ float sm[];
    float* ins  = sm;                 // 3*86*87
    float* ds   = ins + 22446;        // 84*85
    float* red  = ds + 7140;          // 3*9*84
    float* bred = red + 2268;         // 8
    const int tid = threadIdx.x;      // 256
    for (int i = tid; i < 3*86*87; i += 256) {
        int icp = i/(86*87), r = i - icp*(86*87);
        int yy = r/87 - 1, xx = r - (yy+1)*87 - 1;
        float val = 0.f;
        if ((unsigned)yy < 84u && (unsigned)xx < 84u)
            val = xp[(size_t)(n*3+icp)*7056 + yy*84 + xx];
        ins[i] = val;
    }
    const float s = scal[0], sb = scal[1];
    const int icl = tid / 84, rg = tid - icl*84;
    for (int oc8 = 0; oc8 < 32; oc8++) {
        const int oc = oh*32 + oc8;
        __syncthreads();
        const float* dpp = dp0 + (size_t)(n*64+oc)*1764;
        const unsigned char* ipp = i0 + (size_t)(n*64+oc)*1764;
        for (int i = tid; i < 84*85; i += 256) {
            int y = i/85, x = i - y*85;
            float val = 0.f;
            if (x < 84) {
                int py = y>>1, px = x>>1, j = ((y&1)<<1)|(x&1);
                int pi = py*42 + px;
                if (ipp[pi] == j) val = dpp[pi];
            }
            ds[i] = val;
        }
        __syncthreads();
        float bp = 0.f;
        for (int i = tid; i < 84*85; i += 256) bp += ds[i];
        #pragma unroll
        for (int off = 16; off; off >>= 1) bp += __shfl_xor_sync(0xffffffffu, bp, off);
        if ((tid & 31) == 0) bred[tid >> 5] = bp;
        float acc[9];
        #pragma unroll
        for (int k = 0; k < 9; k++) acc[k] = 0.f;
        if (tid < 252) {
            const float* r0p = ins + icl*7482 + rg*87;
            const float* r1p = r0p + 87;
            const float* r2p = r1p + 87;
            const float* dsy = ds + rg*85;
            float a0=r0p[0],a1=r0p[1],b0=r1p[0],b1=r1p[1],c0=r2p[0],c1=r2p[1];
            #pragma unroll 2
            for (int x = 0; x < 84; x++) {
                float a2=r0p[x+2], b2=r1p[x+2], c2=r2p[x+2];
                float d = dsy[x];
                acc[0]+=d*a0; acc[1]+=d*a1; acc[2]+=d*a2;
                acc[3]+=d*b0; acc[4]+=d*b1; acc[5]+=d*b2;
                acc[6]+=d*c0; acc[7]+=d*c1; acc[8]+=d*c2;
                a0=a1;a1=a2;b0=b1;b1=b2;c0=c1;c1=c2;
            }
            #pragma unroll
            for (int k = 0; k < 9; k++) red[(icl*9+k)*84 + rg] = acc[k];
        }
        __syncthreads();
        if (tid == 0) {
            float a = 0.f;
            #pragma unroll
            for (int wq = 0; wq < 8; wq++) a += bred[wq];
            G[(size_t)n*F + OB0 + oc] = sb*a;
        }
        for (int o = tid; o < 27; o += 256) {
            float t2 = 0.f;
            for (int r = 0; r < 84; r++) t2 += red[o*84 + r];
            int icg = o/9, uv = o - icg*9;
            G[(size_t)n*F + OW0 + (oc*3 + icg)*9 + uv] = s*t2;
        }
    }
}

__global__ void copyp3_k(const float* __restrict__ p3, float* __restrict__ G,
                         const float* __restrict__ scal)
{
    int t = blockIdx.x*256 + threadIdx.x;
    if (t >= 128*1600) return;
    int n = t / 1600, j = t - n*1600;
    G[(size_t)n*F + OFC + j] = scal[8]*p3[t];
}

__global__ void gemm_part_k(const float* __restrict__ G, float* __restrict__ part)
{
    const int ty = threadIdx.y, tx = threadIdx.x;
    const int bn = blockIdx.y*16, bm = blockIdx.x*16, sp = blockIdx.z;
    __shared__ float A[16][65], B[16][65];
    const int f0 = sp*(F/8);
    const int tid = ty*16 + tx, row = tid >> 4, q = tid & 15;
    float acc = 0.0f;
    for (int f = f0; f < f0 + F/8; f += 64) {
        float4 a4 = *(const float4*)(G + (size_t)(bn + row)*F + f + q*4);
        float4 b4 = *(const float4*)(G + (size_t)(64 + bm + row)*F + f + q*4);
        A[row][q*4+0] = a4.x; A[row][q*4+1] = a4.y; A[row][q*4+2] = a4.z; A[row][q*4+3] = a4.w;
        B[row][q*4+0] = b4.x; B[row][q*4+1] = b4.y; B[row][q*4+2] = b4.z; B[row][q*4+3] = b4.w;
        __syncthreads();
        #pragma unroll
        for (int k = 0; k < 64; k++) acc += A[ty][k]*B[tx][k];
        __syncthreads();
    }
    part[sp*4096 + (bn + ty)*64 + (bm + tx)] = acc;
}

__global__ void reduce_k(const float* __restrict__ part, const float* __restrict__ scal,
                         float* __restrict__ out)
{
    int t = blockIdx.x*256 + threadIdx.x;
    if (t >= 4096) return;
    float a = scal[9]*scal[9];
    #pragma unroll
    for (int sp = 0; sp < 8; sp++) a += part[sp*4096 + t];
    out[t] = a;
}

// ---------------- host ----------------
extern "C" void kernel_launch(void* const* d_in, const int* in_sizes, int n_in,
                              void* d_out, int out_size)
{
    const float* x1  = (const float*)d_in[0];
    const float* x2  = (const float*)d_in[1];
    const float* scal= (const float*)d_in[2];
    const int*   cp  = (const int*)  d_in[3];
    const float* w0  = (const float*)d_in[4];
    const float* b0  = (const float*)d_in[5];
    const float* w1  = (const float*)d_in[6];
    const float* b1  = (const float*)d_in[7];
    const float* w2  = (const float*)d_in[8];
    const float* b2  = (const float*)d_in[9];
    const float* w3  = (const float*)d_in[10];
    const float* b3  = (const float*)d_in[11];
    const float* fcw = (const float*)d_in[12];
    float* out = (float*)d_out;

    float *xp,*p0,*dp0,*p1,*dp1,*p2,*d3,*dp2,*p3,*wt,*G,*part;
    unsigned char *i0,*i1,*i2,*i3;
    cudaGetSymbolAddress((void**)&xp,  g_x);
    cudaGetSymbolAddress((void**)&p0,  g_p0);
    cudaGetSymbolAddress((void**)&dp0, g_dp0);
    cudaGetSymbolAddress((void**)&i0,  g_i0);
    cudaGetSymbolAddress((void**)&p1,  g_p1);
    cudaGetSymbolAddress((void**)&dp1, g_dp1);
    cudaGetSymbolAddress((void**)&i1,  g_i1);
    cudaGetSymbolAddress((void**)&p2,  g_p2);
    cudaGetSymbolAddress((void**)&d3,  g_d3);
    cudaGetSymbolAddress((void**)&dp2, g_dp2);
    cudaGetSymbolAddress((void**)&i2,  g_i2);
    cudaGetSymbolAddress((void**)&p3,  g_p3);
    cudaGetSymbolAddress((void**)&i3,  g_i3);
    cudaGetSymbolAddress((void**)&wt,  g_wt);
    cudaGetSymbolAddress((void**)&G,   g_G);
    cudaGetSymbolAddress((void**)&part,g_part);

    const int smW0 = (22446 + 7140 + 2268 + 8)*4;
    const int sm42 = (4*42*43)*4 + (8*44*45)*4 + 16;
    const int sm21 = (4*21*21)*4 + (8*23*23)*4 + 16;
    const int sm10 = (4*10*11)*4 + (8*12*13)*4 + 16;

    static bool init = false;
    if (!init) {
        init = true;
        cudaFuncSetAttribute(wgrad0_k, cudaFuncAttributeMaxDynamicSharedMemorySize, smW0);
        cudaFuncSetAttribute(wgrad2_k<64,8>, cudaFuncAttributeMaxDynamicSharedMemorySize, sm42);
    }

    // ---- forward (conv+relu+pool fused, register tiles) ----
    pack_x_k<<<(128*3*84*84 + 255)/256, 256>>>(x1, x2, xp);
    convpool_k<3,1,1> <<<dim3(14,8,128),128>>>(xp, w0, b0, p0, i0, 84, 84, 42, 42);
    convpool_k<64,1,1><<<dim3(4, 8,128),128>>>(p0, w1, b1, p1, i1, 42, 42, 21, 21);
    convpool_k<64,1,1><<<dim3(1, 8,128),128>>>(p1, w2, b2, p2, i2, 21, 21, 10, 10);
    convpool_k<64,5,25><<<dim3(1,8,26),128>>>(p2, w3, b3, p3, i3, 10, 10, 5, 5);

    // ---- backward (scalar output c); unpool fused into conv loads ----
    unpool_fc_k<<<(128*64*100 + 255)/256, 256>>>(fcw, cp, i3, d3);
    transw_k<<<144,256>>>(w3, wt + 0*WTS);
    transw_k<<<144,256>>>(w2, wt + 1*WTS);
    transw_k<<<144,256>>>(w1, wt + 2*WTS);
    conv2_k<64,5,25><<<dim3(1,8,26),128>>>(d3, wt + 0*WTS, dp2, 10, 10);
    conv2f_k<<<dim3(1,8,128),128>>>(dp2, i2, wt + 1*WTS, dp1, 21, 21, 10, 10);
    conv2f_k<<<dim3(4,8,128),128>>>(dp1, i1, wt + 2*WTS, dp0, 42, 42, 21, 21);

    // ---- per-example gradients -> scaled feature matrix G ----
    wgrad0_k<<<dim3(2,128), 256, smW0>>>(dp0, i0, xp, G, scal);
    wgrad2_k<64,8><<<dim3(16,128), 256, sm42>>>(dp1, i1, p0, G, OW1, OB1, scal, 2, 42, 42, 21, 21);
    wgrad2_k<64,8><<<dim3(16,128), 256, sm21>>>(dp2, i2, p1, G, OW2, OB2, scal, 4, 21, 21, 10, 10);
    wgrad2_k<64,8><<<dim3(16,128), 256, sm10>>>(d3, nullptr, p2, G, OW3, OB3, scal, 6, 10, 10, 5, 5);
    copyp3_k<<<(128*1600 + 255)/256, 256>>>(p3, G, scal);

    // ---- K = G1 G2^T + s_fcb^2 ----
    gemm_part_k<<<dim3(4,4,8), dim3(16,16)>>>(G, part);
    reduce_k<<<16,256>>>(part, scal, out);
}